// round 1
// baseline (speedup 1.0000x reference)
#include <cuda_runtime.h>

#define NN 65536
#define HH 128
#define EE 524288

// ---------------- static scratch (no allocations allowed) ----------------
__device__ int   g_deg[3][NN];
__device__ int   g_rowptr[3][NN + 1];
__device__ int   g_cursor[3][NN];
__device__ int   g_col[3][EE];
__device__ float g_h[3][NN * HH];   // 0: h1_r (pass), 1: h2_r (connect), 2: transfer sum

// ---------------- CSR build ----------------
__global__ void k_zero_deg() {
    int i = blockIdx.x * blockDim.x + threadIdx.x;
    if (i < 3 * NN) ((int*)g_deg)[i] = 0;
}

__global__ void k_hist(const int* __restrict__ pass_dst,
                       const int* __restrict__ connect_dst,
                       const int* __restrict__ transfer_dst) {
    int i = blockIdx.x * blockDim.x + threadIdx.x;
    if (i >= 3 * EE) return;
    int r = i / EE, e = i - r * EE;
    const int* dst = (r == 0) ? pass_dst : (r == 1) ? connect_dst : transfer_dst;
    atomicAdd(&g_deg[r][dst[e]], 1);
}

__global__ void k_scan() {
    const int CH = NN / 1024;  // 64 elements per thread
    int r = blockIdx.x;
    int t = threadIdx.x;
    int base = t * CH;
    int s = 0;
    for (int j = 0; j < CH; j++) s += g_deg[r][base + j];

    __shared__ int sm[1024];
    sm[t] = s;
    __syncthreads();
    for (int off = 1; off < 1024; off <<= 1) {
        int v = (t >= off) ? sm[t - off] : 0;
        __syncthreads();
        sm[t] += v;
        __syncthreads();
    }
    int run = sm[t] - s;  // exclusive prefix for this chunk
    for (int j = 0; j < CH; j++) {
        g_rowptr[r][base + j] = run;
        g_cursor[r][base + j] = run;
        run += g_deg[r][base + j];
    }
    if (t == 1023) g_rowptr[r][NN] = run;
}

__global__ void k_fill(const int* __restrict__ pass_src, const int* __restrict__ pass_dst,
                       const int* __restrict__ connect_src, const int* __restrict__ connect_dst,
                       const int* __restrict__ transfer_src, const int* __restrict__ transfer_dst) {
    int i = blockIdx.x * blockDim.x + threadIdx.x;
    if (i >= 3 * EE) return;
    int r = i / EE, e = i - r * EE;
    const int *src, *dst;
    if (r == 0)      { src = pass_src;     dst = pass_dst; }
    else if (r == 1) { src = connect_src;  dst = connect_dst; }
    else             { src = transfer_src; dst = transfer_dst; }
    int d = dst[e];
    int pos = atomicAdd(&g_cursor[r][d], 1);
    g_col[r][pos] = src[e];
}

// ---------------- gather (segment-sum without fp atomics) ----------------
// one warp per (relation, node); lane handles one float4 of the 128-float row
__global__ void k_gather(const float* __restrict__ router_feat,
                         const float* __restrict__ packet_feat) {
    int w = (blockIdx.x * blockDim.x + threadIdx.x) >> 5;
    int lane = threadIdx.x & 31;
    if (w >= 3 * NN) return;
    int r = w >> 16;          // w / NN  (NN = 65536)
    int i = w & (NN - 1);
    const float* ftab = (r == 0) ? packet_feat : router_feat;
    int start = g_rowptr[r][i], end = g_rowptr[r][i + 1];
    float4 acc = {0.f, 0.f, 0.f, 0.f};
    int e = start;
    for (; e + 1 < end; e += 2) {
        int s0 = g_col[r][e], s1 = g_col[r][e + 1];
        float4 a = __ldg((const float4*)(ftab + (size_t)s0 * HH) + lane);
        float4 b = __ldg((const float4*)(ftab + (size_t)s1 * HH) + lane);
        acc.x += a.x + b.x; acc.y += a.y + b.y;
        acc.z += a.z + b.z; acc.w += a.w + b.w;
    }
    if (e < end) {
        int s0 = g_col[r][e];
        float4 a = __ldg((const float4*)(ftab + (size_t)s0 * HH) + lane);
        acc.x += a.x; acc.y += a.y; acc.z += a.z; acc.w += a.w;
    }
    ((float4*)(g_h[r] + (size_t)i * HH))[lane] = acc;
}

// ---------------- fused linear + ReLU + residual ----------------
#define FMA4(A, s, W) { (A).x += (s)*(W).x; (A).y += (s)*(W).y; (A).z += (s)*(W).z; (A).w += (s)*(W).w; }

// router: out = rf + relu(concat(h1r,h2r) @ Wr^T + br), Wr is [128, 256] row-major
__global__ void k_gemm_router(const float* __restrict__ rf, const float* __restrict__ Wr,
                              const float* __restrict__ br, float* __restrict__ out) {
    extern __shared__ float sW[];        // [256][128] : sW[k*128 + j] = Wr[j*256 + k]
    __shared__ float sb[HH];
    int t = threadIdx.x;
    for (int idx = t; idx < 256 * HH; idx += blockDim.x) {
        int j = idx & (HH - 1);
        int k = idx >> 7;
        sW[idx] = Wr[j * 256 + k];
    }
    if (t < HH) sb[t] = br[t];
    __syncthreads();

    int warp = t >> 5, lane = t & 31;
    int nwb = NN / 4;  // 4 rows per warp-iteration
    for (int rb = blockIdx.x * 16 + warp; rb < nwb; rb += gridDim.x * 16) {
        int row0 = rb * 4;
        float4 a0 = {0,0,0,0}, a1 = {0,0,0,0}, a2 = {0,0,0,0}, a3 = {0,0,0,0};
        #pragma unroll
        for (int p = 0; p < 2; p++) {
            const float* hb = g_h[p];
            const float4* x0 = (const float4*)(hb + (size_t)(row0 + 0) * HH);
            const float4* x1 = (const float4*)(hb + (size_t)(row0 + 1) * HH);
            const float4* x2 = (const float4*)(hb + (size_t)(row0 + 2) * HH);
            const float4* x3 = (const float4*)(hb + (size_t)(row0 + 3) * HH);
            int kbase = p * HH;
            #pragma unroll 4
            for (int kb = 0; kb < 32; kb++) {
                float4 v0 = __ldg(x0 + kb), v1 = __ldg(x1 + kb);
                float4 v2 = __ldg(x2 + kb), v3 = __ldg(x3 + kb);
                const float* wb = sW + (size_t)(kbase + kb * 4) * HH + lane * 4;
                float4 w;
                w = *(const float4*)(wb + 0 * HH);
                FMA4(a0, v0.x, w); FMA4(a1, v1.x, w); FMA4(a2, v2.x, w); FMA4(a3, v3.x, w);
                w = *(const float4*)(wb + 1 * HH);
                FMA4(a0, v0.y, w); FMA4(a1, v1.y, w); FMA4(a2, v2.y, w); FMA4(a3, v3.y, w);
                w = *(const float4*)(wb + 2 * HH);
                FMA4(a0, v0.z, w); FMA4(a1, v1.z, w); FMA4(a2, v2.z, w); FMA4(a3, v3.z, w);
                w = *(const float4*)(wb + 3 * HH);
                FMA4(a0, v0.w, w); FMA4(a1, v1.w, w); FMA4(a2, v2.w, w); FMA4(a3, v3.w, w);
            }
        }
        float4 bias = *(const float4*)(sb + lane * 4);
        #pragma unroll
        for (int q = 0; q < 4; q++) {
            float4 a = (q == 0) ? a0 : (q == 1) ? a1 : (q == 2) ? a2 : a3;
            int row = row0 + q;
            float4 res = __ldg((const float4*)(rf + (size_t)row * HH) + lane);
            float4 o;
            o.x = res.x + fmaxf(a.x + bias.x, 0.f);
            o.y = res.y + fmaxf(a.y + bias.y, 0.f);
            o.z = res.z + fmaxf(a.z + bias.z, 0.f);
            o.w = res.w + fmaxf(a.w + bias.w, 0.f);
            ((float4*)(out + (size_t)row * HH))[lane] = o;
        }
    }
}

// packet: out = pf + relu((transfer_sum/max(deg,1)) @ Wp^T + bp), Wp is [128,128] row-major
__global__ void k_gemm_packet(const float* __restrict__ pf, const float* __restrict__ Wp,
                              const float* __restrict__ bp, float* __restrict__ out) {
    extern __shared__ float sW[];        // [128][128] : sW[k*128 + j] = Wp[j*128 + k]
    __shared__ float sb[HH];
    int t = threadIdx.x;
    for (int idx = t; idx < HH * HH; idx += blockDim.x) {
        int j = idx & (HH - 1);
        int k = idx >> 7;
        sW[idx] = Wp[j * HH + k];
    }
    if (t < HH) sb[t] = bp[t];
    __syncthreads();

    int warp = t >> 5, lane = t & 31;
    int nwb = NN / 4;
    for (int rb = blockIdx.x * 16 + warp; rb < nwb; rb += gridDim.x * 16) {
        int row0 = rb * 4;
        float4 a0 = {0,0,0,0}, a1 = {0,0,0,0}, a2 = {0,0,0,0}, a3 = {0,0,0,0};
        const float* hb = g_h[2];
        const float4* x0 = (const float4*)(hb + (size_t)(row0 + 0) * HH);
        const float4* x1 = (const float4*)(hb + (size_t)(row0 + 1) * HH);
        const float4* x2 = (const float4*)(hb + (size_t)(row0 + 2) * HH);
        const float4* x3 = (const float4*)(hb + (size_t)(row0 + 3) * HH);
        #pragma unroll 4
        for (int kb = 0; kb < 32; kb++) {
            float4 v0 = __ldg(x0 + kb), v1 = __ldg(x1 + kb);
            float4 v2 = __ldg(x2 + kb), v3 = __ldg(x3 + kb);
            const float* wb = sW + (size_t)(kb * 4) * HH + lane * 4;
            float4 w;
            w = *(const float4*)(wb + 0 * HH);
            FMA4(a0, v0.x, w); FMA4(a1, v1.x, w); FMA4(a2, v2.x, w); FMA4(a3, v3.x, w);
            w = *(const float4*)(wb + 1 * HH);
            FMA4(a0, v0.y, w); FMA4(a1, v1.y, w); FMA4(a2, v2.y, w); FMA4(a3, v3.y, w);
            w = *(const float4*)(wb + 2 * HH);
            FMA4(a0, v0.z, w); FMA4(a1, v1.z, w); FMA4(a2, v2.z, w); FMA4(a3, v3.z, w);
            w = *(const float4*)(wb + 3 * HH);
            FMA4(a0, v0.w, w); FMA4(a1, v1.w, w); FMA4(a2, v2.w, w); FMA4(a3, v3.w, w);
        }
        float4 bias = *(const float4*)(sb + lane * 4);
        #pragma unroll
        for (int q = 0; q < 4; q++) {
            float4 a = (q == 0) ? a0 : (q == 1) ? a1 : (q == 2) ? a2 : a3;
            int row = row0 + q;
            int d = g_rowptr[2][row + 1] - g_rowptr[2][row];
            float s = 1.0f / (float)max(d, 1);   // mean (zero-degree rows stay 0)
            float4 res = __ldg((const float4*)(pf + (size_t)row * HH) + lane);
            float4 o;
            o.x = res.x + fmaxf(a.x * s + bias.x, 0.f);
            o.y = res.y + fmaxf(a.y * s + bias.y, 0.f);
            o.z = res.z + fmaxf(a.z * s + bias.z, 0.f);
            o.w = res.w + fmaxf(a.w * s + bias.w, 0.f);
            ((float4*)(out + (size_t)row * HH))[lane] = o;
        }
    }
}

// ---------------- launch ----------------
extern "C" void kernel_launch(void* const* d_in, const int* in_sizes, int n_in,
                              void* d_out, int out_size) {
    const float* router_feat  = (const float*)d_in[0];
    const float* packet_feat  = (const float*)d_in[1];
    const float* W_r          = (const float*)d_in[2];
    const float* b_r          = (const float*)d_in[3];
    const float* W_p          = (const float*)d_in[4];
    const float* b_p          = (const float*)d_in[5];
    const int*   pass_src     = (const int*)d_in[6];
    const int*   pass_dst     = (const int*)d_in[7];
    const int*   transfer_src = (const int*)d_in[8];
    const int*   transfer_dst = (const int*)d_in[9];
    const int*   connect_src  = (const int*)d_in[10];
    const int*   connect_dst  = (const int*)d_in[11];
    float* out = (float*)d_out;

    cudaFuncSetAttribute(k_gemm_router, cudaFuncAttributeMaxDynamicSharedMemorySize, 256 * HH * 4);
    cudaFuncSetAttribute(k_gemm_packet, cudaFuncAttributeMaxDynamicSharedMemorySize, HH * HH * 4);

    k_zero_deg<<<(3 * NN + 255) / 256, 256>>>();
    k_hist<<<(3 * EE + 255) / 256, 256>>>(pass_dst, connect_dst, transfer_dst);
    k_scan<<<3, 1024>>>();
    k_fill<<<(3 * EE + 255) / 256, 256>>>(pass_src, pass_dst, connect_src, connect_dst,
                                          transfer_src, transfer_dst);
    k_gather<<<3 * NN / 8, 256>>>(router_feat, packet_feat);
    k_gemm_router<<<148, 512, 256 * HH * 4>>>(router_feat, W_r, b_r, out);
    k_gemm_packet<<<148, 512, HH * HH * 4>>>(packet_feat, W_p, b_p, out + (size_t)NN * HH);
}

// round 2
// speedup vs baseline: 1.3998x; 1.3998x over previous
#include <cuda_runtime.h>
#include <cstdint>

#define NN 65536
#define HH 128
#define EE 524288

// ---------------- static scratch (no allocations allowed) ----------------
__device__ int   g_deg[3][NN];
__device__ int   g_rowptr[3][NN + 1];
__device__ int   g_cursor[3][NN];
__device__ int   g_col[3][EE];
__device__ float g_h[3][NN * HH];   // 0: h1_r (pass), 1: h2_r (connect), 2: transfer sum

// ---------------- CSR build ----------------
__global__ void k_zero_deg() {
    int i = blockIdx.x * blockDim.x + threadIdx.x;
    if (i < 3 * NN) ((int*)g_deg)[i] = 0;
}

__global__ void k_hist(const int* __restrict__ pass_dst,
                       const int* __restrict__ connect_dst,
                       const int* __restrict__ transfer_dst) {
    int i = blockIdx.x * blockDim.x + threadIdx.x;
    if (i >= 3 * EE) return;
    int r = i / EE, e = i - r * EE;
    const int* dst = (r == 0) ? pass_dst : (r == 1) ? connect_dst : transfer_dst;
    atomicAdd(&g_deg[r][dst[e]], 1);
}

__global__ void k_scan() {
    const int CH = NN / 1024;  // 64 elements per thread
    int r = blockIdx.x;
    int t = threadIdx.x;
    int base = t * CH;
    int s = 0;
    for (int j = 0; j < CH; j++) s += g_deg[r][base + j];

    __shared__ int sm[1024];
    sm[t] = s;
    __syncthreads();
    for (int off = 1; off < 1024; off <<= 1) {
        int v = (t >= off) ? sm[t - off] : 0;
        __syncthreads();
        sm[t] += v;
        __syncthreads();
    }
    int run = sm[t] - s;  // exclusive prefix for this chunk
    for (int j = 0; j < CH; j++) {
        g_rowptr[r][base + j] = run;
        g_cursor[r][base + j] = run;
        run += g_deg[r][base + j];
    }
    if (t == 1023) g_rowptr[r][NN] = run;
}

__global__ void k_fill(const int* __restrict__ pass_src, const int* __restrict__ pass_dst,
                       const int* __restrict__ connect_src, const int* __restrict__ connect_dst,
                       const int* __restrict__ transfer_src, const int* __restrict__ transfer_dst) {
    int i = blockIdx.x * blockDim.x + threadIdx.x;
    if (i >= 3 * EE) return;
    int r = i / EE, e = i - r * EE;
    const int *src, *dst;
    if (r == 0)      { src = pass_src;     dst = pass_dst; }
    else if (r == 1) { src = connect_src;  dst = connect_dst; }
    else             { src = transfer_src; dst = transfer_dst; }
    int d = dst[e];
    int pos = atomicAdd(&g_cursor[r][d], 1);
    g_col[r][pos] = src[e];
}

// ---------------- gather (segment-sum without fp atomics) ----------------
__global__ void k_gather(const float* __restrict__ router_feat,
                         const float* __restrict__ packet_feat) {
    int w = (blockIdx.x * blockDim.x + threadIdx.x) >> 5;
    int lane = threadIdx.x & 31;
    if (w >= 3 * NN) return;
    int r = w >> 16;          // w / NN  (NN = 65536)
    int i = w & (NN - 1);
    const float* ftab = (r == 0) ? packet_feat : router_feat;
    int start = g_rowptr[r][i], end = g_rowptr[r][i + 1];
    float4 acc = {0.f, 0.f, 0.f, 0.f};
    int e = start;
    for (; e + 1 < end; e += 2) {
        int s0 = g_col[r][e], s1 = g_col[r][e + 1];
        float4 a = __ldg((const float4*)(ftab + (size_t)s0 * HH) + lane);
        float4 b = __ldg((const float4*)(ftab + (size_t)s1 * HH) + lane);
        acc.x += a.x + b.x; acc.y += a.y + b.y;
        acc.z += a.z + b.z; acc.w += a.w + b.w;
    }
    if (e < end) {
        int s0 = g_col[r][e];
        float4 a = __ldg((const float4*)(ftab + (size_t)s0 * HH) + lane);
        acc.x += a.x; acc.y += a.y; acc.z += a.z; acc.w += a.w;
    }
    ((float4*)(g_h[r] + (size_t)i * HH))[lane] = acc;
}

// ---------------- tf32 tensor-core fused linear + ReLU + residual ----------------
__device__ __forceinline__ uint32_t f2tf32(float x) {
    uint32_t r;
    asm("cvt.rna.tf32.f32 %0, %1;" : "=r"(r) : "f"(x));
    return r;
}

__device__ __forceinline__ void mma_tf32(float* d, const uint32_t* a, const uint32_t* b) {
    asm volatile(
        "mma.sync.aligned.m16n8k8.row.col.f32.tf32.tf32.f32 "
        "{%0,%1,%2,%3},{%4,%5,%6,%7},{%8,%9},{%0,%1,%2,%3};"
        : "+f"(d[0]), "+f"(d[1]), "+f"(d[2]), "+f"(d[3])
        : "r"(a[0]), "r"(a[1]), "r"(a[2]), "r"(a[3]), "r"(b[0]), "r"(b[1]));
}

#define KC 64
#define XS 68   // padded smem stride (floats); 68*4B = 272B, 16B-aligned, conflict-free quads

// Computes out[row, n] = res[row, n] + relu( sum_k X[row,k] * W[n,k] * (scale?) + bias[n] )
// ROUTER: X = concat(g_h[0], g_h[1]) along k (KTOT=256). else: X = g_h[2], KTOT=128, MEAN scaling.
template<int KTOT, bool ROUTER>
__global__ void __launch_bounds__(256, 2) k_gemm_tc(const float* __restrict__ res,
                                                    const float* __restrict__ W,
                                                    const float* __restrict__ bias,
                                                    float* __restrict__ out) {
    extern __shared__ float smem[];
    float* sX = smem;                 // [128][XS]
    float* sW = smem + 128 * XS;      // [128][XS]

    const int t = threadIdx.x;
    const int warp = t >> 5, lane = t & 31;
    const int g = lane >> 2, tg = lane & 3;
    const int mw = (warp & 3) * 32;   // warp row offset within 128-row tile
    const int nw = (warp >> 2) * 64;  // warp col offset within 128-col tile
    const int row0 = blockIdx.x * 128;

    float acc[2][8][4];
    #pragma unroll
    for (int i = 0; i < 2; i++)
        #pragma unroll
        for (int j = 0; j < 8; j++)
            #pragma unroll
            for (int q = 0; q < 4; q++) acc[i][j][q] = 0.f;

    #pragma unroll
    for (int c = 0; c < KTOT / KC; c++) {
        const float* xsrc;
        int koff;
        if (ROUTER) { xsrc = (c < 2) ? g_h[0] : g_h[1]; koff = (c & 1) * KC; }
        else        { xsrc = g_h[2];                    koff = c * KC; }

        __syncthreads();   // previous chunk's compute done before overwrite
        #pragma unroll
        for (int it = 0; it < 8; it++) {
            int idx = it * 256 + t;          // 2048 float4 per buffer
            int row = idx >> 4, c4 = idx & 15;
            float4 xv = __ldg((const float4*)(xsrc + (size_t)(row0 + row) * HH + koff) + c4);
            *(float4*)&sX[row * XS + c4 * 4] = xv;
            float4 wv = __ldg((const float4*)(W + (size_t)row * KTOT + c * KC) + c4);
            *(float4*)&sW[row * XS + c4 * 4] = wv;
        }
        __syncthreads();

        #pragma unroll
        for (int ks = 0; ks < KC / 8; ks++) {
            int k0 = ks * 8;
            uint32_t a[2][4], b[8][2];
            #pragma unroll
            for (int i = 0; i < 2; i++) {
                int r = mw + i * 16 + g;
                a[i][0] = f2tf32(sX[r * XS + k0 + tg]);
                a[i][1] = f2tf32(sX[(r + 8) * XS + k0 + tg]);
                a[i][2] = f2tf32(sX[r * XS + k0 + tg + 4]);
                a[i][3] = f2tf32(sX[(r + 8) * XS + k0 + tg + 4]);
            }
            #pragma unroll
            for (int j = 0; j < 8; j++) {
                int n = nw + j * 8 + g;
                b[j][0] = f2tf32(sW[n * XS + k0 + tg]);
                b[j][1] = f2tf32(sW[n * XS + k0 + tg + 4]);
            }
            #pragma unroll
            for (int i = 0; i < 2; i++)
                #pragma unroll
                for (int j = 0; j < 8; j++)
                    mma_tf32(acc[i][j], a[i], b[j]);
        }
    }

    // ---- epilogue: (mean) + bias + relu + residual ----
    float scl[2][2];
    #pragma unroll
    for (int i = 0; i < 2; i++) {
        if (ROUTER) { scl[i][0] = 1.f; scl[i][1] = 1.f; }
        else {
            int ra = row0 + mw + i * 16 + g;
            int d0 = g_rowptr[2][ra + 1] - g_rowptr[2][ra];
            int d1 = g_rowptr[2][ra + 9] - g_rowptr[2][ra + 8];
            scl[i][0] = 1.f / (float)max(d0, 1);
            scl[i][1] = 1.f / (float)max(d1, 1);
        }
    }

    #pragma unroll
    for (int j = 0; j < 8; j++) {
        int col = nw + j * 8 + 2 * tg;
        float2 bv = *(const float2*)(bias + col);
        #pragma unroll
        for (int i = 0; i < 2; i++) {
            int ra = row0 + mw + i * 16 + g;
            // rows ra (c0,c1) and ra+8 (c2,c3)
            float2 r0v = __ldg((const float2*)(res + (size_t)ra * HH + col));
            float2 r1v = __ldg((const float2*)(res + (size_t)(ra + 8) * HH + col));
            float2 o0, o1;
            o0.x = r0v.x + fmaxf(acc[i][j][0] * scl[i][0] + bv.x, 0.f);
            o0.y = r0v.y + fmaxf(acc[i][j][1] * scl[i][0] + bv.y, 0.f);
            o1.x = r1v.x + fmaxf(acc[i][j][2] * scl[i][1] + bv.x, 0.f);
            o1.y = r1v.y + fmaxf(acc[i][j][3] * scl[i][1] + bv.y, 0.f);
            *(float2*)(out + (size_t)ra * HH + col) = o0;
            *(float2*)(out + (size_t)(ra + 8) * HH + col) = o1;
        }
    }
}

// ---------------- launch ----------------
extern "C" void kernel_launch(void* const* d_in, const int* in_sizes, int n_in,
                              void* d_out, int out_size) {
    const float* router_feat  = (const float*)d_in[0];
    const float* packet_feat  = (const float*)d_in[1];
    const float* W_r          = (const float*)d_in[2];
    const float* b_r          = (const float*)d_in[3];
    const float* W_p          = (const float*)d_in[4];
    const float* b_p          = (const float*)d_in[5];
    const int*   pass_src     = (const int*)d_in[6];
    const int*   pass_dst     = (const int*)d_in[7];
    const int*   transfer_src = (const int*)d_in[8];
    const int*   transfer_dst = (const int*)d_in[9];
    const int*   connect_src  = (const int*)d_in[10];
    const int*   connect_dst  = (const int*)d_in[11];
    float* out = (float*)d_out;

    const int smem_bytes = 2 * 128 * XS * 4;   // 69,632 B
    cudaFuncSetAttribute(k_gemm_tc<256, true>,  cudaFuncAttributeMaxDynamicSharedMemorySize, smem_bytes);
    cudaFuncSetAttribute(k_gemm_tc<128, false>, cudaFuncAttributeMaxDynamicSharedMemorySize, smem_bytes);

    k_zero_deg<<<(3 * NN + 255) / 256, 256>>>();
    k_hist<<<(3 * EE + 255) / 256, 256>>>(pass_dst, connect_dst, transfer_dst);
    k_scan<<<3, 1024>>>();
    k_fill<<<(3 * EE + 255) / 256, 256>>>(pass_src, pass_dst, connect_src, connect_dst,
                                          transfer_src, transfer_dst);
    k_gather<<<3 * NN / 8, 256>>>(router_feat, packet_feat);
    k_gemm_tc<256, true ><<<NN / 128, 256, smem_bytes>>>(router_feat, W_r, b_r, out);
    k_gemm_tc<128, false><<<NN / 128, 256, smem_bytes>>>(packet_feat, W_p, b_p, out + (size_t)NN * HH);
}